// round 6
// baseline (speedup 1.0000x reference)
#include <cuda_runtime.h>
#include <cuda_bf16.h>

#define EPS 0.0001f
#define N_DIFFS 4194304
#define N_TASKS (N_DIFFS / 4)   // 1,048,576 tasks of 4 rows each

__global__ void __launch_bounds__(256, 6)
perf_model_kernel(const float* __restrict__ bin_centers,
                  const int*   __restrict__ obs_idx,
                  const float* __restrict__ lb1p,
                  const float* __restrict__ ub1p,
                  const float* __restrict__ lb2p,
                  const float* __restrict__ ub2p,
                  const float* __restrict__ respp,
                  float* __restrict__ out)
{
    // uniform scalar prep (identical across threads)
    float a1 = __ldg(lb1p), b1 = __ldg(ub1p);
    float a2 = __ldg(lb2p), b2 = __ldg(ub2p);
    float nlb1 = __frcp_rn(1.0f + __expf(-fminf(a1, b1)));
    float nub1 = __frcp_rn(1.0f + __expf(-fmaxf(a1, b1)));
    float nlb2 = __frcp_rn(1.0f + __expf(-fminf(a2, b2)));
    float nub2 = __frcp_rn(1.0f + __expf(-fmaxf(a2, b2)));
    float r    = __frcp_rn(1.0f + __expf(-__ldg(respp)));
    float inv1 = __frcp_rn(nub1 - nlb1 + EPS);
    float inv2 = __frcp_rn(nub2 - nlb2 + EPS);
    float c1 = nub1 * inv1;
    float c2 = nub2 * inv2;

    const int stride = gridDim.x * blockDim.x;
    int i = blockIdx.x * blockDim.x + threadIdx.x;

    const int4* base = reinterpret_cast<const int4*>(obs_idx);
    float4* outv = reinterpret_cast<float4*>(out);

    // prologue: load first task's indices (streaming, evict-first)
    int4 a0 = __ldcs(base + 3 * i + 0);
    int4 a1v = __ldcs(base + 3 * i + 1);
    int4 a2v = __ldcs(base + 3 * i + 2);

    for (;;) {
        int j = i + stride;
        bool more = (j < N_TASKS);
        int jj = more ? j : i;           // safe address; result discarded if !more

        // PREFETCH next task's stream loads BEFORE current compute
        int4 b0 = __ldcs(base + 3 * jj + 0);
        int4 b1v = __ldcs(base + 3 * jj + 1);
        int4 b2v = __ldcs(base + 3 * jj + 2);

        // current task: gathers from L1-resident 4KB table
        float x0a = __ldg(bin_centers + a0.x),  x0b = __ldg(bin_centers + a0.y);
        float x1a = __ldg(bin_centers + a0.w),  x1b = __ldg(bin_centers + a1v.x);
        float x2a = __ldg(bin_centers + a1v.z), x2b = __ldg(bin_centers + a1v.w);
        float x3a = __ldg(bin_centers + a2v.y), x3b = __ldg(bin_centers + a2v.z);

        // perf factor = saturate((ub - x) * inv) = saturate(fma(-x, inv, ub*inv))
        float4 o;
        o.x = __saturatef(fmaf(-x0a, inv1, c1)) * __saturatef(fmaf(-x0b, inv2, c2)) * r;
        o.y = __saturatef(fmaf(-x1a, inv1, c1)) * __saturatef(fmaf(-x1b, inv2, c2)) * r;
        o.z = __saturatef(fmaf(-x2a, inv1, c1)) * __saturatef(fmaf(-x2b, inv2, c2)) * r;
        o.w = __saturatef(fmaf(-x3a, inv1, c1)) * __saturatef(fmaf(-x3b, inv2, c2)) * r;

        outv[i] = o;

        if (!more) break;
        a0 = b0; a1v = b1v; a2v = b2v;
        i = j;
    }
}

extern "C" void kernel_launch(void* const* d_in, const int* in_sizes, int n_in,
                              void* d_out, int out_size)
{
    // metadata order: bin_centers, obs_idx, lb1, ub1, lb2, ub2, resp
    const float* bin_centers = (const float*)d_in[0];
    const int*   obs_idx     = (const int*)  d_in[1];
    const float* lb1         = (const float*)d_in[2];
    const float* ub1         = (const float*)d_in[3];
    const float* lb2         = (const float*)d_in[4];
    const float* ub2         = (const float*)d_in[5];
    const float* resp        = (const float*)d_in[6];
    float* out = (float*)d_out;

    const int threads = 256;
    const int blocks = 148 * 6;   // 888 CTAs: single wave at occ 6

    perf_model_kernel<<<blocks, threads>>>(bin_centers, obs_idx,
                                           lb1, ub1, lb2, ub2, resp, out);
}

// round 7
// speedup vs baseline: 1.5702x; 1.5702x over previous
#include <cuda_runtime.h>
#include <cuda_bf16.h>
#include <cstdint>

#define EPS 0.0001f
#define N_DIFFS 4194304
#define ROWS_PER_CTA 1024                 // 256 threads * 4 rows
#define IDX_INTS_PER_CTA (ROWS_PER_CTA * 3)   // 3072 ints = 12288 bytes
#define IDX_BYTES_PER_CTA (IDX_INTS_PER_CTA * 4)

__device__ __forceinline__ uint32_t smem_u32(const void* p) {
    uint32_t a;
    asm("{ .reg .u64 t; cvta.to.shared.u64 t, %1; cvt.u32.u64 %0, t; }" : "=r"(a) : "l"(p));
    return a;
}

__global__ void __launch_bounds__(256)
perf_model_kernel(const float* __restrict__ bin_centers,
                  const int*   __restrict__ obs_idx,
                  const float* __restrict__ lb1p,
                  const float* __restrict__ ub1p,
                  const float* __restrict__ lb2p,
                  const float* __restrict__ ub2p,
                  const float* __restrict__ respp,
                  float* __restrict__ out)
{
    __shared__ alignas(128) int s_idx[IDX_INTS_PER_CTA];
    __shared__ alignas(8) uint64_t s_mbar;

    int tid = threadIdx.x;
    uint32_t mbar = smem_u32(&s_mbar);

    if (tid == 0) {
        asm volatile("mbarrier.init.shared.b64 [%0], 1;" :: "r"(mbar) : "memory");
    }
    __syncthreads();

    if (tid == 0) {
        asm volatile("mbarrier.arrive.expect_tx.shared.b64 _, [%0], %1;"
                     :: "r"(mbar), "r"((uint32_t)IDX_BYTES_PER_CTA) : "memory");
        const char* src = reinterpret_cast<const char*>(obs_idx)
                        + (long long)blockIdx.x * IDX_BYTES_PER_CTA;
        asm volatile("cp.async.bulk.shared::cluster.global.mbarrier::complete_tx::bytes "
                     "[%0], [%1], %2, [%3];"
                     :: "r"(smem_u32(s_idx)), "l"(src),
                        "r"((uint32_t)IDX_BYTES_PER_CTA), "r"(mbar) : "memory");
    }

    // uniform scalar prep — overlaps the TMA transfer
    float a1 = __ldg(lb1p), b1 = __ldg(ub1p);
    float a2 = __ldg(lb2p), b2 = __ldg(ub2p);
    float nlb1 = __frcp_rn(1.0f + __expf(-fminf(a1, b1)));
    float nub1 = __frcp_rn(1.0f + __expf(-fmaxf(a1, b1)));
    float nlb2 = __frcp_rn(1.0f + __expf(-fminf(a2, b2)));
    float nub2 = __frcp_rn(1.0f + __expf(-fmaxf(a2, b2)));
    float r    = __frcp_rn(1.0f + __expf(-__ldg(respp)));
    float inv1 = __frcp_rn(nub1 - nlb1 + EPS);
    float inv2 = __frcp_rn(nub2 - nlb2 + EPS);
    float c1 = nub1 * inv1;
    float c2 = nub2 * inv2;

    // wait for the bulk copy (parity 0, single phase per launch)
    {
        uint32_t done;
        asm volatile(
            "{\n\t"
            ".reg .pred p;\n\t"
            "mbarrier.try_wait.parity.shared.b64 p, [%1], 0;\n\t"
            "selp.b32 %0, 1, 0, p;\n\t"
            "}" : "=r"(done) : "r"(mbar) : "memory");
        while (!done) {
            asm volatile(
                "{\n\t"
                ".reg .pred p;\n\t"
                "mbarrier.try_wait.parity.shared.b64 p, [%1], 0, 0x989680;\n\t"
                "selp.b32 %0, 1, 0, p;\n\t"
                "}" : "=r"(done) : "r"(mbar) : "memory");
        }
    }

    // read this thread's 12 indices: 3x LDS.128, conflict-free
    const int4* sp = reinterpret_cast<const int4*>(s_idx) + tid * 3;
    int4 v0 = sp[0];
    int4 v1 = sp[1];
    int4 v2 = sp[2];

    // gathers from the L1-resident (now unpolluted) 4KB table
    float x0a = __ldg(bin_centers + v0.x), x0b = __ldg(bin_centers + v0.y);
    float x1a = __ldg(bin_centers + v0.w), x1b = __ldg(bin_centers + v1.x);
    float x2a = __ldg(bin_centers + v1.z), x2b = __ldg(bin_centers + v1.w);
    float x3a = __ldg(bin_centers + v2.y), x3b = __ldg(bin_centers + v2.z);

    // perf factor = saturate((ub - x) * inv) = saturate(fma(-x, inv, ub*inv))
    float4 o;
    o.x = __saturatef(fmaf(-x0a, inv1, c1)) * __saturatef(fmaf(-x0b, inv2, c2)) * r;
    o.y = __saturatef(fmaf(-x1a, inv1, c1)) * __saturatef(fmaf(-x1b, inv2, c2)) * r;
    o.z = __saturatef(fmaf(-x2a, inv1, c1)) * __saturatef(fmaf(-x2b, inv2, c2)) * r;
    o.w = __saturatef(fmaf(-x3a, inv1, c1)) * __saturatef(fmaf(-x3b, inv2, c2)) * r;

    long long task = (long long)blockIdx.x * 256 + tid;
    reinterpret_cast<float4*>(out)[task] = o;
}

extern "C" void kernel_launch(void* const* d_in, const int* in_sizes, int n_in,
                              void* d_out, int out_size)
{
    // metadata order: bin_centers, obs_idx, lb1, ub1, lb2, ub2, resp
    const float* bin_centers = (const float*)d_in[0];
    const int*   obs_idx     = (const int*)  d_in[1];
    const float* lb1         = (const float*)d_in[2];
    const float* ub1         = (const float*)d_in[3];
    const float* lb2         = (const float*)d_in[4];
    const float* ub2         = (const float*)d_in[5];
    const float* resp        = (const float*)d_in[6];
    float* out = (float*)d_out;

    const int threads = 256;
    const int blocks = N_DIFFS / ROWS_PER_CTA;   // 4096

    perf_model_kernel<<<blocks, threads>>>(bin_centers, obs_idx,
                                           lb1, ub1, lb2, ub2, resp, out);
}